// round 5
// baseline (speedup 1.0000x reference)
#include <cuda_runtime.h>
#include <cuda_bf16.h>

#define T_DIM 16384
#define H_DIM 4096
#define EPS 1e-5f

// Scratch (allocation-free rule: __device__ globals). 256 MB each.
__device__ float g_y[(size_t)T_DIM * H_DIM];
__device__ float g_r[(size_t)T_DIM * H_DIM];

// ---------------------------------------------------------------------------
// RMSNorm: one block per row, 256 threads, 16 floats/thread kept in registers.
// RELU_IN applies relu to the input before the norm (first norm's input is
// relu(x)).
// ---------------------------------------------------------------------------
template<bool RELU_IN>
__global__ void __launch_bounds__(256) rmsnorm_kernel(
    const float* __restrict__ in, const float* __restrict__ g,
    float* __restrict__ out)
{
    const int row = blockIdx.x;
    const float4* inp  = reinterpret_cast<const float4*>(in + (size_t)row * H_DIM);
    float4*       outp = reinterpret_cast<float4*>(out + (size_t)row * H_DIM);
    const float4* gp   = reinterpret_cast<const float4*>(g);

    float4 v[4];
    float ssq = 0.f;
    #pragma unroll
    for (int i = 0; i < 4; i++) {
        float4 t = inp[threadIdx.x + i * 256];
        if (RELU_IN) {
            t.x = fmaxf(t.x, 0.f); t.y = fmaxf(t.y, 0.f);
            t.z = fmaxf(t.z, 0.f); t.w = fmaxf(t.w, 0.f);
        }
        v[i] = t;
        ssq += t.x * t.x + t.y * t.y + t.z * t.z + t.w * t.w;
    }

    __shared__ float red[8];
    #pragma unroll
    for (int o = 16; o > 0; o >>= 1) ssq += __shfl_xor_sync(0xffffffffu, ssq, o);
    const int wid = threadIdx.x >> 5, lid = threadIdx.x & 31;
    if (lid == 0) red[wid] = ssq;
    __syncthreads();
    if (wid == 0) {
        float s = (lid < 8) ? red[lid] : 0.f;
        #pragma unroll
        for (int o = 4; o > 0; o >>= 1) s += __shfl_xor_sync(0xffffffffu, s, o);
        if (lid == 0) red[0] = rsqrtf(s * (1.0f / H_DIM) + EPS);
    }
    __syncthreads();
    const float rs = red[0];

    #pragma unroll
    for (int i = 0; i < 4; i++) {
        float4 gg = gp[threadIdx.x + i * 256];
        float4 t = v[i];
        t.x *= rs * gg.x; t.y *= rs * gg.y; t.z *= rs * gg.z; t.w *= rs * gg.w;
        outp[threadIdx.x + i * 256] = t;
    }
}

// ---------------------------------------------------------------------------
// SGEMM C = A @ B + addend, fused epilogue.
//   MODE 0: addend = relu(addsrc[idx])   (addsrc = x; C = fresh resid buffer)
//   MODE 1: addend = addsrc[idx]         (addsrc == C: in-place resid update;
//                                         each element read once, written once
//                                         by the same thread -> safe)
// Tile: 128x128 per block, BK=8, 8x8 per thread, 256 threads, 2 blocks/SM.
// Register prefetch of next global tiles to hide LDG latency behind the
// 512-FFMA-per-warp compute body.
// NOTE: no __restrict__ on addsrc/C (they alias in MODE 1).
// ---------------------------------------------------------------------------
template<int MODE>
__global__ void __launch_bounds__(256, 2) gemm_add_kernel(
    const float* __restrict__ A, const float* __restrict__ B,
    const float* addsrc, float* C)
{
    __shared__ float As[8][128];
    __shared__ float Bs[8][128];

    const int tid = threadIdx.x;
    const int tx = tid & 15;        // output col group (0..15)
    const int ty = tid >> 4;        // output row group (0..15)

    const int rowBase = blockIdx.y * 128;
    const int colBase = blockIdx.x * 128;

    // A tile load mapping: 128 rows x 8 k, one float4 per thread
    const int arow = tid >> 1;          // 0..127
    const int acol = (tid & 1) * 4;     // 0 or 4
    // B tile load mapping: 8 k-rows x 128 cols, one float4 per thread
    const int brow = tid >> 5;          // 0..7
    const int bcol = (tid & 31) * 4;    // 0..124

    const float* Ag = A + (size_t)(rowBase + arow) * H_DIM + acol;
    const float* Bg = B + (size_t)brow * H_DIM + colBase + bcol;

    float acc[8][8];
    #pragma unroll
    for (int i = 0; i < 8; i++)
        #pragma unroll
        for (int j = 0; j < 8; j++) acc[i][j] = 0.f;

    // prefetch first tiles
    float4 a4 = *reinterpret_cast<const float4*>(Ag);
    float4 b4 = *reinterpret_cast<const float4*>(Bg);

    for (int k0 = 0; k0 < H_DIM; k0 += 8) {
        As[acol + 0][arow] = a4.x;
        As[acol + 1][arow] = a4.y;
        As[acol + 2][arow] = a4.z;
        As[acol + 3][arow] = a4.w;
        *reinterpret_cast<float4*>(&Bs[brow][bcol]) = b4;
        __syncthreads();

        if (k0 + 8 < H_DIM) {   // prefetch next tiles while computing
            a4 = *reinterpret_cast<const float4*>(Ag + k0 + 8);
            b4 = *reinterpret_cast<const float4*>(Bg + (size_t)(k0 + 8) * H_DIM);
        }

        #pragma unroll
        for (int kk = 0; kk < 8; kk++) {
            float a[8], b[8];
            *reinterpret_cast<float4*>(&a[0]) = *reinterpret_cast<float4*>(&As[kk][ty * 8]);
            *reinterpret_cast<float4*>(&a[4]) = *reinterpret_cast<float4*>(&As[kk][ty * 8 + 4]);
            *reinterpret_cast<float4*>(&b[0]) = *reinterpret_cast<float4*>(&Bs[kk][tx * 8]);
            *reinterpret_cast<float4*>(&b[4]) = *reinterpret_cast<float4*>(&Bs[kk][tx * 8 + 4]);
            #pragma unroll
            for (int i = 0; i < 8; i++)
                #pragma unroll
                for (int j = 0; j < 8; j++)
                    acc[i][j] = fmaf(a[i], b[j], acc[i][j]);
        }
        __syncthreads();
    }

    // fused epilogue
    #pragma unroll
    for (int i = 0; i < 8; i++) {
        const int row = rowBase + ty * 8 + i;
        const size_t base = (size_t)row * H_DIM + colBase + tx * 8;
        #pragma unroll
        for (int j2 = 0; j2 < 2; j2++) {
            float4 add = *reinterpret_cast<const float4*>(addsrc + base + j2 * 4);
            if (MODE == 0) {
                add.x = fmaxf(add.x, 0.f); add.y = fmaxf(add.y, 0.f);
                add.z = fmaxf(add.z, 0.f); add.w = fmaxf(add.w, 0.f);
            }
            float4 o;
            o.x = acc[i][j2 * 4 + 0] + add.x;
            o.y = acc[i][j2 * 4 + 1] + add.y;
            o.z = acc[i][j2 * 4 + 2] + add.z;
            o.w = acc[i][j2 * 4 + 3] + add.w;
            *reinterpret_cast<float4*>(C + base + j2 * 4) = o;
        }
    }
}

// ---------------------------------------------------------------------------
// Pipeline:
//   y = rmsnorm(relu(x), g0)
//   r = y @ w0 + relu(x)
//   y = rmsnorm(r, g1)
//   r = y @ w1 + r        (in-place)
//   out = rmsnorm(r, g2)
// ---------------------------------------------------------------------------
extern "C" void kernel_launch(void* const* d_in, const int* in_sizes, int n_in,
                              void* d_out, int out_size) {
    const float* x  = (const float*)d_in[0];
    const float* g0 = (const float*)d_in[1];
    const float* g1 = (const float*)d_in[2];
    const float* g2 = (const float*)d_in[3];
    const float* w0 = (const float*)d_in[4];
    const float* w1 = (const float*)d_in[5];
    float* out = (float*)d_out;

    float *y = nullptr, *r = nullptr;
    cudaGetSymbolAddress((void**)&y, g_y);
    cudaGetSymbolAddress((void**)&r, g_r);

    dim3 gridN(T_DIM);
    dim3 gridG(H_DIM / 128, T_DIM / 128);

    rmsnorm_kernel<true ><<<gridN, 256>>>(x, g0, y);
    gemm_add_kernel<0>   <<<gridG, 256>>>(y, w0, x, r);
    rmsnorm_kernel<false><<<gridN, 256>>>(r, g1, y);
    gemm_add_kernel<1>   <<<gridG, 256>>>(y, w1, r, r);
    rmsnorm_kernel<false><<<gridN, 256>>>(r, g2, out);
}

// round 6
// speedup vs baseline: 1.0010x; 1.0010x over previous
#include <cuda_runtime.h>
#include <cuda_bf16.h>

#define T_DIM 16384
#define H_DIM 4096
#define EPS 1e-5f

// Scratch (allocation-free rule: __device__ globals). 256 MB each.
__device__ float g_y[(size_t)T_DIM * H_DIM];
__device__ float g_r[(size_t)T_DIM * H_DIM];

// ---------------------------------------------------------------------------
// RMSNorm: one block per row, 256 threads, 16 floats/thread kept in registers.
// RELU_IN applies relu to the input before the norm (first norm's input is
// relu(x)).
// ---------------------------------------------------------------------------
template<bool RELU_IN>
__global__ void __launch_bounds__(256) rmsnorm_kernel(
    const float* __restrict__ in, const float* __restrict__ g,
    float* __restrict__ out)
{
    const int row = blockIdx.x;
    const float4* inp  = reinterpret_cast<const float4*>(in + (size_t)row * H_DIM);
    float4*       outp = reinterpret_cast<float4*>(out + (size_t)row * H_DIM);
    const float4* gp   = reinterpret_cast<const float4*>(g);

    float4 v[4];
    float ssq = 0.f;
    #pragma unroll
    for (int i = 0; i < 4; i++) {
        float4 t = inp[threadIdx.x + i * 256];
        if (RELU_IN) {
            t.x = fmaxf(t.x, 0.f); t.y = fmaxf(t.y, 0.f);
            t.z = fmaxf(t.z, 0.f); t.w = fmaxf(t.w, 0.f);
        }
        v[i] = t;
        ssq += t.x * t.x + t.y * t.y + t.z * t.z + t.w * t.w;
    }

    __shared__ float red[8];
    #pragma unroll
    for (int o = 16; o > 0; o >>= 1) ssq += __shfl_xor_sync(0xffffffffu, ssq, o);
    const int wid = threadIdx.x >> 5, lid = threadIdx.x & 31;
    if (lid == 0) red[wid] = ssq;
    __syncthreads();
    if (wid == 0) {
        float s = (lid < 8) ? red[lid] : 0.f;
        #pragma unroll
        for (int o = 4; o > 0; o >>= 1) s += __shfl_xor_sync(0xffffffffu, s, o);
        if (lid == 0) red[0] = rsqrtf(s * (1.0f / H_DIM) + EPS);
    }
    __syncthreads();
    const float rs = red[0];

    #pragma unroll
    for (int i = 0; i < 4; i++) {
        float4 gg = gp[threadIdx.x + i * 256];
        float4 t = v[i];
        t.x *= rs * gg.x; t.y *= rs * gg.y; t.z *= rs * gg.z; t.w *= rs * gg.w;
        outp[threadIdx.x + i * 256] = t;
    }
}

// ---------------------------------------------------------------------------
// SGEMM C = A @ B + addend, fused epilogue.
//   MODE 0: addend = relu(addsrc[idx])   (addsrc = x; C = fresh resid buffer)
//   MODE 1: addend = addsrc[idx]         (addsrc == C: in-place resid update;
//                                         each element read once, written once
//                                         by the same thread -> safe)
// Tile: 128x128 per block, BK=8, 8x8 per thread, 256 threads, 2 blocks/SM.
// Register prefetch of next global tiles to hide LDG latency behind the
// 512-FFMA-per-warp compute body.
// NOTE: no __restrict__ on addsrc/C (they alias in MODE 1).
// ---------------------------------------------------------------------------
template<int MODE>
__global__ void __launch_bounds__(256, 2) gemm_add_kernel(
    const float* __restrict__ A, const float* __restrict__ B,
    const float* addsrc, float* C)
{
    __shared__ float As[8][128];
    __shared__ float Bs[8][128];

    const int tid = threadIdx.x;
    const int tx = tid & 15;        // output col group (0..15)
    const int ty = tid >> 4;        // output row group (0..15)

    const int rowBase = blockIdx.y * 128;
    const int colBase = blockIdx.x * 128;

    // A tile load mapping: 128 rows x 8 k, one float4 per thread
    const int arow = tid >> 1;          // 0..127
    const int acol = (tid & 1) * 4;     // 0 or 4
    // B tile load mapping: 8 k-rows x 128 cols, one float4 per thread
    const int brow = tid >> 5;          // 0..7
    const int bcol = (tid & 31) * 4;    // 0..124

    const float* Ag = A + (size_t)(rowBase + arow) * H_DIM + acol;
    const float* Bg = B + (size_t)brow * H_DIM + colBase + bcol;

    float acc[8][8];
    #pragma unroll
    for (int i = 0; i < 8; i++)
        #pragma unroll
        for (int j = 0; j < 8; j++) acc[i][j] = 0.f;

    // prefetch first tiles
    float4 a4 = *reinterpret_cast<const float4*>(Ag);
    float4 b4 = *reinterpret_cast<const float4*>(Bg);

    for (int k0 = 0; k0 < H_DIM; k0 += 8) {
        As[acol + 0][arow] = a4.x;
        As[acol + 1][arow] = a4.y;
        As[acol + 2][arow] = a4.z;
        As[acol + 3][arow] = a4.w;
        *reinterpret_cast<float4*>(&Bs[brow][bcol]) = b4;
        __syncthreads();

        if (k0 + 8 < H_DIM) {   // prefetch next tiles while computing
            a4 = *reinterpret_cast<const float4*>(Ag + k0 + 8);
            b4 = *reinterpret_cast<const float4*>(Bg + (size_t)(k0 + 8) * H_DIM);
        }

        #pragma unroll
        for (int kk = 0; kk < 8; kk++) {
            float a[8], b[8];
            *reinterpret_cast<float4*>(&a[0]) = *reinterpret_cast<float4*>(&As[kk][ty * 8]);
            *reinterpret_cast<float4*>(&a[4]) = *reinterpret_cast<float4*>(&As[kk][ty * 8 + 4]);
            *reinterpret_cast<float4*>(&b[0]) = *reinterpret_cast<float4*>(&Bs[kk][tx * 8]);
            *reinterpret_cast<float4*>(&b[4]) = *reinterpret_cast<float4*>(&Bs[kk][tx * 8 + 4]);
            #pragma unroll
            for (int i = 0; i < 8; i++)
                #pragma unroll
                for (int j = 0; j < 8; j++)
                    acc[i][j] = fmaf(a[i], b[j], acc[i][j]);
        }
        __syncthreads();
    }

    // fused epilogue
    #pragma unroll
    for (int i = 0; i < 8; i++) {
        const int row = rowBase + ty * 8 + i;
        const size_t base = (size_t)row * H_DIM + colBase + tx * 8;
        #pragma unroll
        for (int j2 = 0; j2 < 2; j2++) {
            float4 add = *reinterpret_cast<const float4*>(addsrc + base + j2 * 4);
            if (MODE == 0) {
                add.x = fmaxf(add.x, 0.f); add.y = fmaxf(add.y, 0.f);
                add.z = fmaxf(add.z, 0.f); add.w = fmaxf(add.w, 0.f);
            }
            float4 o;
            o.x = acc[i][j2 * 4 + 0] + add.x;
            o.y = acc[i][j2 * 4 + 1] + add.y;
            o.z = acc[i][j2 * 4 + 2] + add.z;
            o.w = acc[i][j2 * 4 + 3] + add.w;
            *reinterpret_cast<float4*>(C + base + j2 * 4) = o;
        }
    }
}

// ---------------------------------------------------------------------------
// Pipeline:
//   y = rmsnorm(relu(x), g0)
//   r = y @ w0 + relu(x)
//   y = rmsnorm(r, g1)
//   r = y @ w1 + r        (in-place)
//   out = rmsnorm(r, g2)
// ---------------------------------------------------------------------------
extern "C" void kernel_launch(void* const* d_in, const int* in_sizes, int n_in,
                              void* d_out, int out_size) {
    const float* x  = (const float*)d_in[0];
    const float* g0 = (const float*)d_in[1];
    const float* g1 = (const float*)d_in[2];
    const float* g2 = (const float*)d_in[3];
    const float* w0 = (const float*)d_in[4];
    const float* w1 = (const float*)d_in[5];
    float* out = (float*)d_out;

    float *y = nullptr, *r = nullptr;
    cudaGetSymbolAddress((void**)&y, g_y);
    cudaGetSymbolAddress((void**)&r, g_r);

    dim3 gridN(T_DIM);
    dim3 gridG(H_DIM / 128, T_DIM / 128);

    rmsnorm_kernel<true ><<<gridN, 256>>>(x, g0, y);
    gemm_add_kernel<0>   <<<gridG, 256>>>(y, w0, x, r);
    rmsnorm_kernel<false><<<gridN, 256>>>(r, g1, y);
    gemm_add_kernel<1>   <<<gridG, 256>>>(y, w1, r, r);
    rmsnorm_kernel<false><<<gridN, 256>>>(r, g2, out);
}